// round 12
// baseline (speedup 1.0000x reference)
#include <cuda_runtime.h>
#include <math.h>

#define BATCH 32
#define HH 256
#define WW 256
#define IMGPIX 65536
#define IMGWORDS 2048
#define NWORDS (BATCH*IMGWORDS)
#define INF_I 10000
#define K1B 256                  // 32 img x 8 rowgroups of 32 rows
#define RB   1024                // 32 img x 32 bands of 8 rows

__device__ unsigned int g_tgm[NWORDS];
__device__ unsigned int g_fatm[NWORDS];
__device__ unsigned int g_fatT[BATCH * 8 * 256];   // [img][rowword 0..7][col]
__device__ int   g_fgp[K1B];
__device__ int   g_bmin[RB], g_bmax[RB];
__device__ float g_s1[RB], g_s2[RB], g_s4[RB], g_s5[RB], g_s6[RB], g_s7[RB];
__device__ int   g_count;        // zero-init; last block resets

__device__ __forceinline__ float fsum32(float v) {
#pragma unroll
    for (int s = 16; s > 0; s >>= 1) v += __shfl_down_sync(0xffffffffu, v, s);
    return v;
}
__device__ __forceinline__ int imin32(int v) {
#pragma unroll
    for (int s = 16; s > 0; s >>= 1) v = min(v, __shfl_down_sync(0xffffffffu, v, s));
    return v;
}
__device__ __forceinline__ int imax32(int v) {
#pragma unroll
    for (int s = 16; s > 0; s >>= 1) v = max(v, __shfl_down_sync(0xffffffffu, v, s));
    return v;
}
__device__ __forceinline__ unsigned int ior32(unsigned int v) {
#pragma unroll
    for (int s = 16; s > 0; s >>= 1) v |= __shfl_down_sync(0xffffffffu, v, s);
    return v;
}

__device__ __forceinline__ float fast_sigmoid(float x) {
    float y;
    asm("tanh.approx.f32 %0, %1;" : "=f"(y) : "f"(x * 0.5f));
    return fmaf(y, 0.5f, 0.5f);
}

// sigmoid(sqrt(best)/5) with zero fast path
__device__ __forceinline__ float soft_of(int best) {
    if (best == 0) return 0.5f;
    float dist = sqrtf((float)best);
    float y;
    asm("tanh.approx.f32 %0, %1;" : "=f"(y) : "f"(dist * 0.1f));
    return fmaf(y, 0.5f, 0.5f);
}

// first zero bit at row >= s in 256-bit column mask; returns distance from s (INF_I if none)
__device__ __forceinline__ int down_search(const unsigned int* m, int s) {
    if (s > 255) return INF_I;
    int w = s >> 5, b = s & 31;
    unsigned int x = (~m[w]) >> b;
    if (x) return __ffs(x) - 1;
    int d = INF_I;
    for (int k = w + 1; k < 8; k++) {
        unsigned int xi = ~m[k];
        if (xi) { d = k * 32 + __ffs(xi) - 1 - s; break; }
    }
    return d;
}
// first zero bit at row <= s; returns distance from s (INF_I if none)
__device__ __forceinline__ int up_search(const unsigned int* m, int s) {
    if (s < 0) return INF_I;
    int w = s >> 5, b = s & 31;
    unsigned int y = (~m[w]) << (31 - b);
    if (y) return __clz(y);
    int d = INF_I;
    for (int k = w - 1; k >= 0; k--) {
        unsigned int yi = ~m[k];
        if (yi) { d = s - (k * 32 + 31 - __clz(yi)); break; }
    }
    return d;
}

// ---- K1: fused mask build + 5x5 bitwise dilate + bit-transpose ----
__global__ void k_maskdilate(const float4* __restrict__ tg4) {
    __shared__ unsigned long long nibs8[288];
    __shared__ unsigned int raw[288];
    __shared__ unsigned int hm[288];
    __shared__ unsigned int fatw[256];
    __shared__ unsigned int s_fg[8];
    unsigned char* nibs = (unsigned char*)nibs8;
    const int tid = threadIdx.x, lane = tid & 31, wid = tid >> 5;
    const int img = blockIdx.x >> 3, rg = blockIdx.x & 7;
    const int r0 = rg * 32;
    const int img4 = img * (IMGPIX / 4);

    float4 v[9];
#pragma unroll
    for (int k = 0; k < 9; k++) {
        int q = k * 256 + tid;
        int lr = q >> 6;
        int grow = r0 - 2 + lr;
        float4 val = make_float4(0.f, 0.f, 0.f, 0.f);
        if (grow >= 0 && grow < HH) val = tg4[img4 + grow * 64 + (q & 63)];
        v[k] = val;
    }
#pragma unroll
    for (int k = 0; k < 9; k++) {
        unsigned int nib = (v[k].x > 0.5f ? 1u : 0u) | (v[k].y > 0.5f ? 2u : 0u) |
                           (v[k].z > 0.5f ? 4u : 0u) | (v[k].w > 0.5f ? 8u : 0u);
        nibs[k * 256 + tid] = (unsigned char)nib;
    }
    __syncthreads();

    unsigned int fgacc = 0u;
    for (int w = tid; w < 288; w += 256) {
        unsigned long long n8 = nibs8[w];
        unsigned int a = (unsigned int)n8;
        unsigned int b = (unsigned int)(n8 >> 32);
        a &= 0x0F0F0F0Fu; a = (a | (a >> 4)) & 0x00FF00FFu; a = (a | (a >> 8)) & 0x0000FFFFu;
        b &= 0x0F0F0F0Fu; b = (b | (b >> 4)) & 0x00FF00FFu; b = (b | (b >> 8)) & 0x0000FFFFu;
        unsigned int word = a | (b << 16);
        raw[w] = word;
        int lr = w >> 3;
        if (lr >= 2 && lr < 34) {
            fgacc |= word;
            g_tgm[img * IMGWORDS + (r0 + lr - 2) * 8 + (w & 7)] = word;
        }
    }
    fgacc = ior32(fgacc);
    if (lane == 0) s_fg[wid] = fgacc;
    __syncthreads();
    if (tid == 0) {
        unsigned int a = 0;
#pragma unroll
        for (int i = 0; i < 8; i++) a |= s_fg[i];
        g_fgp[blockIdx.x] = a ? 1 : 0;
    }

    for (int w = tid; w < 288; w += 256) {
        int wc = w & 7;
        unsigned int c  = raw[w];
        unsigned int ml = (wc > 0) ? raw[w - 1] : 0u;
        unsigned int mr = (wc < 7) ? raw[w + 1] : 0u;
        unsigned int h = c;
        h |= (c << 1) | (ml >> 31);
        h |= (c << 2) | (ml >> 30);
        h |= (c >> 1) | (mr << 31);
        h |= (c >> 2) | (mr << 30);
        hm[w] = h;
    }
    __syncthreads();
    {
        int rl = tid >> 3, wc = tid & 7;
        unsigned int f = hm[rl * 8 + wc] | hm[(rl + 1) * 8 + wc] | hm[(rl + 2) * 8 + wc] |
                         hm[(rl + 3) * 8 + wc] | hm[(rl + 4) * 8 + wc];
        fatw[tid] = f;
        g_fatm[img * IMGWORDS + (r0 + rl) * 8 + wc] = f;
    }
    __syncthreads();
    {
        unsigned int vv = fatw[lane * 8 + wid];
        unsigned int myw = 0u;
#pragma unroll
        for (int c = 0; c < 32; c++) {
            unsigned int bw = __ballot_sync(0xffffffffu, (vv >> c) & 1u);
            if (lane == c) myw = bw;
        }
        g_fatT[img * 2048 + rg * 256 + wid * 32 + lane] = myw;
    }
}

// ---- K2: fused vertical-dist + pruned min-plus + partials + last-block finish ----
__global__ void k_rowfuse(const float* __restrict__ preds, float* __restrict__ out) {
    __shared__ unsigned short tile[8 * WW];
    __shared__ unsigned int stgw[64], sfatw[64];
    __shared__ float sf[8][6];
    __shared__ int smn8[8], smx8[8];
    __shared__ int s_isLast;
    const int tid = threadIdx.x;
    const int img = blockIdx.x >> 5, band = blockIdx.x & 31;
    const int r0 = band * 8;
    const int base = img * IMGPIX + r0 * WW;
    const int wb = img * IMGWORDS + r0 * 8;

    if (tid < 64) { stgw[tid] = g_tgm[wb + tid]; sfatw[tid] = g_fatm[wb + tid]; }

    unsigned int m[8];
#pragma unroll
    for (int k = 0; k < 8; k++) m[k] = g_fatT[img * 2048 + k * 256 + tid];

    // preds prefetch (MLP 8)
    float pv[8];
#pragma unroll
    for (int i = 0; i < 8; i++) pv[i] = preds[base + i * WW + tid];

    // vertical distances for 8 consecutive rows via recurrence
    {
        unsigned int window = (m[r0 >> 5] >> (r0 & 31)) & 0xFFu;   // bits r0..r0+7
        int Darr[8];
        int cur = down_search(m, r0 + 8);
#pragma unroll
        for (int i = 7; i >= 0; i--) {
            cur = ((window >> i) & 1u) ? min(cur + 1, INF_I) : 0;
            Darr[i] = cur;
        }
        cur = up_search(m, r0 - 1);
#pragma unroll
        for (int i = 0; i < 8; i++) {
            cur = ((window >> i) & 1u) ? min(cur + 1, INF_I) : 0;
            tile[i * WW + tid] = (unsigned short)min(Darr[i], cur);
        }
    }
    __syncthreads();

    const int j = tid;
    const int wsel = j >> 5, bsel = j & 31;
    float s1 = 0, s2 = 0, s4 = 0, s5 = 0, s6 = 0, s7 = 0;
    int mn = 0x7fffffff, mx = 0;
#pragma unroll 1
    for (int i = 0; i < 8; i++) {
        const unsigned short* grow = tile + i * WW;
        int g0 = grow[j];
        int best = g0 * g0;
        int r2 = 1;
        for (int rad = 1; rad < WW; rad++) {
            if (r2 >= best) break;
            int jl = j - rad, jr = j + rad;
            if (jl >= 0) { int gv = grow[jl]; best = min(best, gv * gv + r2); }
            if (jr < WW) { int gv = grow[jr]; best = min(best, gv * gv + r2); }
            r2 += 2 * rad + 1;
        }
        mn = min(mn, best); mx = max(mx, best);
        float soft = soft_of(best);
        float p = fast_sigmoid(pv[i]);
        float t    = (float)((stgw[(i << 3) | wsel]  >> bsel) & 1u);
        float fatb = (float)((sfatw[(i << 3) | wsel] >> bsel) & 1u);
        float ps = p * soft;
        s1 += ps * t;
        s2 += p * t;
        s4 += ps;
        s5 += p;
        s6 += p * (1.0f - fatb);
        s7 += t;
    }
    mn = imin32(mn); mx = imax32(mx);

    // single-stage block reduction
    float v0 = fsum32(s1), v1 = fsum32(s2), v2 = fsum32(s4);
    float v3 = fsum32(s5), v4 = fsum32(s6), v5 = fsum32(s7);
    const int lane = tid & 31, wid = tid >> 5;
    if (lane == 0) {
        sf[wid][0] = v0; sf[wid][1] = v1; sf[wid][2] = v2;
        sf[wid][3] = v3; sf[wid][4] = v4; sf[wid][5] = v5;
        smn8[wid] = mn; smx8[wid] = mx;
    }
    __syncthreads();
    if (tid < 6) {
        float a = 0;
#pragma unroll
        for (int i = 0; i < 8; i++) a += sf[i][tid];
        float* outs[6] = {g_s1, g_s2, g_s4, g_s5, g_s6, g_s7};
        outs[tid][blockIdx.x] = a;
    } else if (tid == 8) {
        int a = smn8[0];
#pragma unroll
        for (int i = 1; i < 8; i++) a = min(a, smn8[i]);
        g_bmin[blockIdx.x] = a;
    } else if (tid == 9) {
        int b = smx8[0];
#pragma unroll
        for (int i = 1; i < 8; i++) b = max(b, smx8[i]);
        g_bmax[blockIdx.x] = b;
    }

    // ---- last-block finisher ----
    if (tid == 0) {
        __threadfence();
        int old = atomicAdd(&g_count, 1);
        s_isLast = (old == RB - 1) ? 1 : 0;
    }
    __syncthreads();
    if (!s_isLast) return;
    if (tid == 0) g_count = 0;
    __threadfence();

    __shared__ float a1[256], a2[256], a4[256], a5[256], a6[256], a7[256];
    __shared__ int amn[256], amx[256];
    {
        const int t = tid;
        const int im = t >> 3, seg = t & 7;
        float S1 = 0, S2 = 0, S4 = 0, S5 = 0, S6 = 0, S7 = 0;
        int mnl = 0x7fffffff, mxl = 0;
#pragma unroll
        for (int q = 0; q < 4; q++) {
            int k = im * 32 + seg * 4 + q;
            S1 += g_s1[k]; S2 += g_s2[k]; S4 += g_s4[k];
            S5 += g_s5[k]; S6 += g_s6[k]; S7 += g_s7[k];
            mnl = min(mnl, g_bmin[k]); mxl = max(mxl, g_bmax[k]);
        }
        a1[t] = S1; a2[t] = S2; a4[t] = S4; a5[t] = S5; a6[t] = S6; a7[t] = S7;
        amn[t] = mnl; amx[t] = mxl;
    }
    __syncthreads();
    if (tid < 32) {
        const int i = tid;
        float S1 = 0, S2 = 0, S4 = 0, S5 = 0, S6 = 0, S7 = 0;
        int mnl = 0x7fffffff, mxl = 0;
#pragma unroll
        for (int s = 0; s < 8; s++) {
            int k = i * 8 + s;
            S1 += a1[k]; S2 += a2[k]; S4 += a4[k];
            S5 += a5[k]; S6 += a6[k]; S7 += a7[k];
            mnl = min(mnl, amn[k]); mxl = max(mxl, amx[k]);
        }
        int fg = 0;
#pragma unroll
        for (int rg = 0; rg < 8; rg++) fg |= g_fgp[i * 8 + rg];
        float inter, card;
        if (fg) {
            float smn = soft_of(mnl);
            float smx = soft_of(mxl);
            float dd = smx - smn;
            float inv = (dd > 0.0f) ? (1.0f / dd) : 1.0f;
            inter = inv * (S1 - smn * S2);
            card  = inv * (S4 - smn * S5) + 0.1f * S6 + S7;
        } else {
            inter = 0.0f;
            card  = (S5 - S2) + S7;
        }
        float tsum = S7;
        inter = fsum32(inter);
        card  = fsum32(card);
        tsum  = fsum32(tsum);
        if (i == 0) {
            float dice = 2.0f * inter / fmaxf(card, 1e-7f);
            float loss = 1.0f - dice;
            out[0] = (tsum > 0.0f) ? loss : 0.0f;
        }
    }
}

extern "C" void kernel_launch(void* const* d_in, const int* in_sizes, int n_in,
                              void* d_out, int out_size) {
    const float* preds = (const float*)d_in[0];
    const float* tg    = (const float*)d_in[1];
    float* out = (float*)d_out;

    k_maskdilate<<<K1B, 256>>>((const float4*)tg);
    k_rowfuse<<<RB, 256>>>(preds, out);
}

// round 13
// speedup vs baseline: 1.2150x; 1.2150x over previous
#include <cuda_runtime.h>
#include <math.h>

#define BATCH 32
#define HH 256
#define WW 256
#define IMGPIX 65536
#define IMGWORDS 2048
#define NWORDS (BATCH*IMGWORDS)
#define INF_I 10000
#define K1B 256                  // dilate tasks: 32 img x 8 rowgroups of 32 rows
#define RB   1024                // rowfuse tasks: 32 img x 32 bands of 8 rows
#define GRID 512                 // blocks (all co-resident at 4 blocks/SM)

__device__ unsigned int g_tgm[NWORDS];
__device__ unsigned int g_fatm[NWORDS];
__device__ unsigned int g_fatT[BATCH * 8 * 256];   // [img][rowword 0..7][col]
__device__ int   g_fgp[K1B];
__device__ int   g_bmin[RB], g_bmax[RB];
__device__ float g_s1[RB], g_s2[RB], g_s4[RB], g_s5[RB], g_s6[RB], g_s7[RB];
__device__ int   g_count;        // zero-init; finisher resets
__device__ int   g_done;         // zero-init; finisher resets

__device__ __forceinline__ float fsum32(float v) {
#pragma unroll
    for (int s = 16; s > 0; s >>= 1) v += __shfl_down_sync(0xffffffffu, v, s);
    return v;
}
__device__ __forceinline__ int imin32(int v) {
#pragma unroll
    for (int s = 16; s > 0; s >>= 1) v = min(v, __shfl_down_sync(0xffffffffu, v, s));
    return v;
}
__device__ __forceinline__ int imax32(int v) {
#pragma unroll
    for (int s = 16; s > 0; s >>= 1) v = max(v, __shfl_down_sync(0xffffffffu, v, s));
    return v;
}
__device__ __forceinline__ unsigned int ior32(unsigned int v) {
#pragma unroll
    for (int s = 16; s > 0; s >>= 1) v |= __shfl_down_sync(0xffffffffu, v, s);
    return v;
}

__device__ __forceinline__ float fast_sigmoid(float x) {
    float y;
    asm("tanh.approx.f32 %0, %1;" : "=f"(y) : "f"(x * 0.5f));
    return fmaf(y, 0.5f, 0.5f);
}

// sigmoid(sqrt(best)/5) with zero fast path
__device__ __forceinline__ float soft_of(int best) {
    if (best == 0) return 0.5f;
    float dist = sqrtf((float)best);
    float y;
    asm("tanh.approx.f32 %0, %1;" : "=f"(y) : "f"(dist * 0.1f));
    return fmaf(y, 0.5f, 0.5f);
}

// distance (in rows) from position r to nearest 0-bit in 256-bit column mask m[8]
__device__ __forceinline__ int nzdist(const unsigned int* m, int r) {
    int w = r >> 5, b = r & 31;
    unsigned int inv0 = ~m[w];
    int dd;
    unsigned int x = inv0 >> b;
    if (x) dd = __ffs(x) - 1;
    else {
        dd = INF_I;
        for (int k = w + 1; k < 8; k++) {
            unsigned int xi = ~m[k];
            if (xi) { dd = k * 32 + __ffs(xi) - 1 - r; break; }
        }
    }
    int du;
    unsigned int y = inv0 << (31 - b);
    if (y) du = __clz(y);
    else {
        du = INF_I;
        for (int k = w - 1; k >= 0; k--) {
            unsigned int yi = ~m[k];
            if (yi) { du = r - (k * 32 + 31 - __clz(yi)); break; }
        }
    }
    return min(min(dd, du), INF_I);
}

__global__ void __launch_bounds__(256, 4)
k_fused(const float4* __restrict__ tg4, const float* __restrict__ preds,
        float* __restrict__ out) {
    // ---- dilate-phase smem ----
    __shared__ unsigned long long nibs8[288];
    __shared__ unsigned int raw[288];
    __shared__ unsigned int hm[288];
    __shared__ unsigned int fatw[256];
    __shared__ unsigned int s_fg[8];
    // ---- rowfuse-phase smem ----
    __shared__ unsigned short tile[8 * WW];
    __shared__ unsigned int stgw[64], sfatw[64];
    __shared__ float sf[8][6];
    __shared__ int smn8[8], smx8[8];
    __shared__ int s_isLast;

    const int tid = threadIdx.x, lane = tid & 31, wid = tid >> 5;
    const int bid = blockIdx.x;
    unsigned char* nibs = (unsigned char*)nibs8;

    // ================= phase A: mask build + dilate + transpose (blocks 0..255) ===========
    if (bid < K1B) {
        const int img = bid >> 3, rg = bid & 7;
        const int r0 = rg * 32;
        const int img4 = img * (IMGPIX / 4);

        float4 v[9];
#pragma unroll
        for (int k = 0; k < 9; k++) {
            int q = k * 256 + tid;
            int lr = q >> 6;
            int grow = r0 - 2 + lr;
            float4 val = make_float4(0.f, 0.f, 0.f, 0.f);
            if (grow >= 0 && grow < HH) val = tg4[img4 + grow * 64 + (q & 63)];
            v[k] = val;
        }
#pragma unroll
        for (int k = 0; k < 9; k++) {
            unsigned int nib = (v[k].x > 0.5f ? 1u : 0u) | (v[k].y > 0.5f ? 2u : 0u) |
                               (v[k].z > 0.5f ? 4u : 0u) | (v[k].w > 0.5f ? 8u : 0u);
            nibs[k * 256 + tid] = (unsigned char)nib;
        }
        __syncthreads();

        unsigned int fgacc = 0u;
        for (int w = tid; w < 288; w += 256) {
            unsigned long long n8 = nibs8[w];
            unsigned int a = (unsigned int)n8;
            unsigned int b = (unsigned int)(n8 >> 32);
            a &= 0x0F0F0F0Fu; a = (a | (a >> 4)) & 0x00FF00FFu; a = (a | (a >> 8)) & 0x0000FFFFu;
            b &= 0x0F0F0F0Fu; b = (b | (b >> 4)) & 0x00FF00FFu; b = (b | (b >> 8)) & 0x0000FFFFu;
            unsigned int word = a | (b << 16);
            raw[w] = word;
            int lr = w >> 3;
            if (lr >= 2 && lr < 34) {
                fgacc |= word;
                g_tgm[img * IMGWORDS + (r0 + lr - 2) * 8 + (w & 7)] = word;
            }
        }
        fgacc = ior32(fgacc);
        if (lane == 0) s_fg[wid] = fgacc;
        __syncthreads();
        if (tid == 0) {
            unsigned int a = 0;
#pragma unroll
            for (int i = 0; i < 8; i++) a |= s_fg[i];
            g_fgp[bid] = a ? 1 : 0;
        }

        for (int w = tid; w < 288; w += 256) {
            int wc = w & 7;
            unsigned int c  = raw[w];
            unsigned int ml = (wc > 0) ? raw[w - 1] : 0u;
            unsigned int mr = (wc < 7) ? raw[w + 1] : 0u;
            unsigned int h = c;
            h |= (c << 1) | (ml >> 31);
            h |= (c << 2) | (ml >> 30);
            h |= (c >> 1) | (mr << 31);
            h |= (c >> 2) | (mr << 30);
            hm[w] = h;
        }
        __syncthreads();
        {
            int rl = tid >> 3, wc = tid & 7;
            unsigned int f = hm[rl * 8 + wc] | hm[(rl + 1) * 8 + wc] | hm[(rl + 2) * 8 + wc] |
                             hm[(rl + 3) * 8 + wc] | hm[(rl + 4) * 8 + wc];
            fatw[tid] = f;
            g_fatm[img * IMGWORDS + (r0 + rl) * 8 + wc] = f;
        }
        __syncthreads();
        {
            unsigned int vv = fatw[lane * 8 + wid];
            unsigned int myw = 0u;
#pragma unroll
            for (int c = 0; c < 32; c++) {
                unsigned int bw = __ballot_sync(0xffffffffu, (vv >> c) & 1u);
                if (lane == c) myw = bw;
            }
            g_fatT[img * 2048 + rg * 256 + wid * 32 + lane] = myw;
        }
        __threadfence();
        __syncthreads();
        if (tid == 0) atomicAdd(&g_done, 1);
    }

    // ================= prefetch first task's preds, then wait for dilate ==================
    int task = bid;
    int img = task >> 5, band = task & 31;
    int r0 = band * 8;
    int base = img * IMGPIX + r0 * WW;
    float pv[8];
#pragma unroll
    for (int i = 0; i < 8; i++) pv[i] = preds[base + i * WW + tid];

    if (tid == 0) {
        while (atomicAdd(&g_done, 0) < K1B) __nanosleep(64);
    }
    __syncthreads();
    __threadfence();

    // ================= phase B: rowfuse tasks (2 per block) ===============================
    while (true) {
        const int wb = img * IMGWORDS + r0 * 8;
        if (tid < 64) { stgw[tid] = g_tgm[wb + tid]; sfatw[tid] = g_fatm[wb + tid]; }

        unsigned int m[8];
#pragma unroll
        for (int k = 0; k < 8; k++) m[k] = g_fatT[img * 2048 + k * 256 + tid];

#pragma unroll
        for (int i = 0; i < 8; i++) {
            int r = r0 + i;
            int d = ((m[r >> 5] >> (r & 31)) & 1u) ? nzdist(m, r) : 0;
            tile[i * WW + tid] = (unsigned short)d;
        }
        __syncthreads();

        const int j = tid;
        const int wsel = j >> 5, bsel = j & 31;
        float s1 = 0, s2 = 0, s4 = 0, s5 = 0, s6 = 0, s7 = 0;
        int mn = 0x7fffffff, mx = 0;
#pragma unroll 1
        for (int i = 0; i < 8; i++) {
            const unsigned short* grow = tile + i * WW;
            int g0 = grow[j];
            int best = g0 * g0;
            int r2 = 1;
            for (int rad = 1; rad < WW; rad++) {
                if (r2 >= best) break;
                int jl = j - rad, jr = j + rad;
                if (jl >= 0) { int gv = grow[jl]; best = min(best, gv * gv + r2); }
                if (jr < WW) { int gv = grow[jr]; best = min(best, gv * gv + r2); }
                r2 += 2 * rad + 1;
            }
            mn = min(mn, best); mx = max(mx, best);
            float soft = soft_of(best);
            float p = fast_sigmoid(pv[i]);
            float t    = (float)((stgw[(i << 3) | wsel]  >> bsel) & 1u);
            float fatb = (float)((sfatw[(i << 3) | wsel] >> bsel) & 1u);
            float ps = p * soft;
            s1 += ps * t;
            s2 += p * t;
            s4 += ps;
            s5 += p;
            s6 += p * (1.0f - fatb);
            s7 += t;
        }
        mn = imin32(mn); mx = imax32(mx);

        float v0 = fsum32(s1), v1 = fsum32(s2), v2 = fsum32(s4);
        float v3 = fsum32(s5), v4 = fsum32(s6), v5 = fsum32(s7);
        if (lane == 0) {
            sf[wid][0] = v0; sf[wid][1] = v1; sf[wid][2] = v2;
            sf[wid][3] = v3; sf[wid][4] = v4; sf[wid][5] = v5;
            smn8[wid] = mn; smx8[wid] = mx;
        }
        __syncthreads();
        if (tid < 6) {
            float a = 0;
#pragma unroll
            for (int i = 0; i < 8; i++) a += sf[i][tid];
            float* outs[6] = {g_s1, g_s2, g_s4, g_s5, g_s6, g_s7};
            outs[tid][task] = a;
        } else if (tid == 8) {
            int a = smn8[0];
#pragma unroll
            for (int i = 1; i < 8; i++) a = min(a, smn8[i]);
            g_bmin[task] = a;
        } else if (tid == 9) {
            int b = smx8[0];
#pragma unroll
            for (int i = 1; i < 8; i++) b = max(b, smx8[i]);
            g_bmax[task] = b;
        }

        task += GRID;
        if (task >= RB) break;
        img = task >> 5; band = task & 31;
        r0 = band * 8;
        base = img * IMGPIX + r0 * WW;
#pragma unroll
        for (int i = 0; i < 8; i++) pv[i] = preds[base + i * WW + tid];
        __syncthreads();
    }

    // ================= last-block finisher =================================================
    __threadfence();
    __syncthreads();
    if (tid == 0) {
        int old = atomicAdd(&g_count, 1);
        s_isLast = (old == GRID - 1) ? 1 : 0;
    }
    __syncthreads();
    if (!s_isLast) return;
    if (tid == 0) { g_count = 0; g_done = 0; }
    __threadfence();

    __shared__ float a1[256], a2[256], a4[256], a5[256], a6[256], a7[256];
    __shared__ int amn[256], amx[256];
    {
        const int t = tid;
        const int im = t >> 3, seg = t & 7;
        float S1 = 0, S2 = 0, S4 = 0, S5 = 0, S6 = 0, S7 = 0;
        int mnl = 0x7fffffff, mxl = 0;
#pragma unroll
        for (int q = 0; q < 4; q++) {
            int k = im * 32 + seg * 4 + q;
            S1 += g_s1[k]; S2 += g_s2[k]; S4 += g_s4[k];
            S5 += g_s5[k]; S6 += g_s6[k]; S7 += g_s7[k];
            mnl = min(mnl, g_bmin[k]); mxl = max(mxl, g_bmax[k]);
        }
        a1[t] = S1; a2[t] = S2; a4[t] = S4; a5[t] = S5; a6[t] = S6; a7[t] = S7;
        amn[t] = mnl; amx[t] = mxl;
    }
    __syncthreads();
    if (tid < 32) {
        const int i = tid;
        float S1 = 0, S2 = 0, S4 = 0, S5 = 0, S6 = 0, S7 = 0;
        int mnl = 0x7fffffff, mxl = 0;
#pragma unroll
        for (int s = 0; s < 8; s++) {
            int k = i * 8 + s;
            S1 += a1[k]; S2 += a2[k]; S4 += a4[k];
            S5 += a5[k]; S6 += a6[k]; S7 += a7[k];
            mnl = min(mnl, amn[k]); mxl = max(mxl, amx[k]);
        }
        int fg = 0;
#pragma unroll
        for (int rg = 0; rg < 8; rg++) fg |= g_fgp[i * 8 + rg];
        float inter, card;
        if (fg) {
            float smn = soft_of(mnl);
            float smx = soft_of(mxl);
            float dd = smx - smn;
            float inv = (dd > 0.0f) ? (1.0f / dd) : 1.0f;
            inter = inv * (S1 - smn * S2);
            card  = inv * (S4 - smn * S5) + 0.1f * S6 + S7;
        } else {
            inter = 0.0f;
            card  = (S5 - S2) + S7;
        }
        float tsum = S7;
        inter = fsum32(inter);
        card  = fsum32(card);
        tsum  = fsum32(tsum);
        if (i == 0) {
            float dice = 2.0f * inter / fmaxf(card, 1e-7f);
            float loss = 1.0f - dice;
            out[0] = (tsum > 0.0f) ? loss : 0.0f;
        }
    }
}

extern "C" void kernel_launch(void* const* d_in, const int* in_sizes, int n_in,
                              void* d_out, int out_size) {
    const float* preds = (const float*)d_in[0];
    const float* tg    = (const float*)d_in[1];
    float* out = (float*)d_out;

    k_fused<<<GRID, 256>>>((const float4*)tg, preds, out);
}

// round 15
// speedup vs baseline: 1.3848x; 1.1398x over previous
#include <cuda_runtime.h>
#include <math.h>

#define BATCH 32
#define HH 256
#define WW 256
#define IMGPIX 65536
#define IMGWORDS 2048
#define NWORDS (BATCH*IMGWORDS)
#define DCAP 255
#define K1B 256                  // 32 img x 8 rowgroups of 32 rows
#define RB   1024                // 32 img x 32 bands of 8 rows

__device__ unsigned int g_tgm[NWORDS];
__device__ unsigned int g_fatm[NWORDS];
__device__ unsigned int g_fatT[BATCH * 8 * 256];   // [img][rowword 0..7][col]
__device__ int   g_fgp[K1B];
__device__ int   g_bmin[RB], g_bmax[RB];
__device__ float g_s1[RB], g_s2[RB], g_s4[RB], g_s5[RB], g_s6[RB], g_s7[RB];
__device__ int   g_count;        // zero-init; last block resets

__device__ __forceinline__ float fsum32(float v) {
#pragma unroll
    for (int s = 16; s > 0; s >>= 1) v += __shfl_down_sync(0xffffffffu, v, s);
    return v;
}
__device__ __forceinline__ int imin32(int v) {
#pragma unroll
    for (int s = 16; s > 0; s >>= 1) v = min(v, __shfl_down_sync(0xffffffffu, v, s));
    return v;
}
__device__ __forceinline__ int imax32(int v) {
#pragma unroll
    for (int s = 16; s > 0; s >>= 1) v = max(v, __shfl_down_sync(0xffffffffu, v, s));
    return v;
}
__device__ __forceinline__ unsigned int ior32(unsigned int v) {
#pragma unroll
    for (int s = 16; s > 0; s >>= 1) v |= __shfl_down_sync(0xffffffffu, v, s);
    return v;
}

__device__ __forceinline__ float fast_sigmoid(float x) {
    float y;
    asm("tanh.approx.f32 %0, %1;" : "=f"(y) : "f"(x * 0.5f));
    return fmaf(y, 0.5f, 0.5f);
}

// sigmoid(sqrt(best)/5) with zero fast path
__device__ __forceinline__ float soft_of(int best) {
    if (best == 0) return 0.5f;
    float dist = sqrtf((float)best);
    float y;
    asm("tanh.approx.f32 %0, %1;" : "=f"(y) : "f"(dist * 0.1f));
    return fmaf(y, 0.5f, 0.5f);
}

// distance (in rows, capped at DCAP) to nearest 0-bit in 256-bit column mask m[8]
__device__ __forceinline__ int nzdist(const unsigned int* m, int r) {
    int w = r >> 5, b = r & 31;
    unsigned int inv0 = ~m[w];
    int dd;
    unsigned int x = inv0 >> b;
    if (x) dd = __ffs(x) - 1;
    else {
        dd = DCAP;
        for (int k = w + 1; k < 8; k++) {
            unsigned int xi = ~m[k];
            if (xi) { dd = k * 32 + __ffs(xi) - 1 - r; break; }
        }
    }
    int du;
    unsigned int y = inv0 << (31 - b);
    if (y) du = __clz(y);
    else {
        du = DCAP;
        for (int k = w - 1; k >= 0; k--) {
            unsigned int yi = ~m[k];
            if (yi) { du = r - (k * 32 + 31 - __clz(yi)); break; }
        }
    }
    return min(min(dd, du), DCAP);
}

// ---- K1: fused mask build + 5x5 bitwise dilate + bit-transpose ----
__global__ void k_maskdilate(const float4* __restrict__ tg4) {
    __shared__ unsigned long long nibs8[288];
    __shared__ unsigned int raw[288];
    __shared__ unsigned int hm[288];
    __shared__ unsigned int fatw[256];
    __shared__ unsigned int s_fg[8];
    unsigned char* nibs = (unsigned char*)nibs8;
    const int tid = threadIdx.x, lane = tid & 31, wid = tid >> 5;
    const int img = blockIdx.x >> 3, rg = blockIdx.x & 7;
    const int r0 = rg * 32;
    const int img4 = img * (IMGPIX / 4);

    float4 v[9];
#pragma unroll
    for (int k = 0; k < 9; k++) {
        int q = k * 256 + tid;
        int lr = q >> 6;
        int grow = r0 - 2 + lr;
        float4 val = make_float4(0.f, 0.f, 0.f, 0.f);
        if (grow >= 0 && grow < HH) val = tg4[img4 + grow * 64 + (q & 63)];
        v[k] = val;
    }
#pragma unroll
    for (int k = 0; k < 9; k++) {
        unsigned int nib = (v[k].x > 0.5f ? 1u : 0u) | (v[k].y > 0.5f ? 2u : 0u) |
                           (v[k].z > 0.5f ? 4u : 0u) | (v[k].w > 0.5f ? 8u : 0u);
        nibs[k * 256 + tid] = (unsigned char)nib;
    }
    __syncthreads();

    unsigned int fgacc = 0u;
    for (int w = tid; w < 288; w += 256) {
        unsigned long long n8 = nibs8[w];
        unsigned int a = (unsigned int)n8;
        unsigned int b = (unsigned int)(n8 >> 32);
        a &= 0x0F0F0F0Fu; a = (a | (a >> 4)) & 0x00FF00FFu; a = (a | (a >> 8)) & 0x0000FFFFu;
        b &= 0x0F0F0F0Fu; b = (b | (b >> 4)) & 0x00FF00FFu; b = (b | (b >> 8)) & 0x0000FFFFu;
        unsigned int word = a | (b << 16);
        raw[w] = word;
        int lr = w >> 3;
        if (lr >= 2 && lr < 34) {
            fgacc |= word;
            g_tgm[img * IMGWORDS + (r0 + lr - 2) * 8 + (w & 7)] = word;
        }
    }
    fgacc = ior32(fgacc);
    if (lane == 0) s_fg[wid] = fgacc;
    __syncthreads();
    if (tid == 0) {
        unsigned int a = 0;
#pragma unroll
        for (int i = 0; i < 8; i++) a |= s_fg[i];
        g_fgp[blockIdx.x] = a ? 1 : 0;
    }

    for (int w = tid; w < 288; w += 256) {
        int wc = w & 7;
        unsigned int c  = raw[w];
        unsigned int ml = (wc > 0) ? raw[w - 1] : 0u;
        unsigned int mr = (wc < 7) ? raw[w + 1] : 0u;
        unsigned int h = c;
        h |= (c << 1) | (ml >> 31);
        h |= (c << 2) | (ml >> 30);
        h |= (c >> 1) | (mr << 31);
        h |= (c >> 2) | (mr << 30);
        hm[w] = h;
    }
    __syncthreads();
    {
        int rl = tid >> 3, wc = tid & 7;
        unsigned int f = hm[rl * 8 + wc] | hm[(rl + 1) * 8 + wc] | hm[(rl + 2) * 8 + wc] |
                         hm[(rl + 3) * 8 + wc] | hm[(rl + 4) * 8 + wc];
        fatw[tid] = f;
        g_fatm[img * IMGWORDS + (r0 + rl) * 8 + wc] = f;
    }
    __syncthreads();
    {
        unsigned int vv = fatw[lane * 8 + wid];
        unsigned int myw = 0u;
#pragma unroll
        for (int c = 0; c < 32; c++) {
            unsigned int bw = __ballot_sync(0xffffffffu, (vv >> c) & 1u);
            if (lane == c) myw = bw;
        }
        g_fatT[img * 2048 + rg * 256 + wid * 32 + lane] = myw;
    }
}

// ---- K2: fused vertical-dist + pruned min-plus + partials + last-block finish ----
__global__ void k_rowfuse(const float* __restrict__ preds, float* __restrict__ out) {
    __shared__ unsigned short tile[8 * WW];      // stores d^2 (u16)
    __shared__ unsigned int stgw[64], sfatw[64];
    __shared__ float sf[8][6];
    __shared__ int smn8[8], smx8[8];
    __shared__ int s_isLast;
    const int tid = threadIdx.x;
    const int img = blockIdx.x >> 5, band = blockIdx.x & 31;
    const int r0 = band * 8;
    const int base = img * IMGPIX + r0 * WW;
    const int wb = img * IMGWORDS + r0 * 8;

    if (tid < 64) { stgw[tid] = g_tgm[wb + tid]; sfatw[tid] = g_fatm[wb + tid]; }

    unsigned int m[8];
#pragma unroll
    for (int k = 0; k < 8; k++) m[k] = g_fatT[img * 2048 + k * 256 + tid];

    // preds prefetch (MLP 8)
    float pv[8];
#pragma unroll
    for (int i = 0; i < 8; i++) pv[i] = preds[base + i * WW + tid];

#pragma unroll
    for (int i = 0; i < 8; i++) {
        int r = r0 + i;
        int d = ((m[r >> 5] >> (r & 31)) & 1u) ? nzdist(m, r) : 0;
        tile[i * WW + tid] = (unsigned short)(d * d);
    }
    __syncthreads();

    const int j = tid;
    const int wsel = j >> 5, bsel = j & 31;
    float s1 = 0, s2 = 0, s4 = 0, s5 = 0, s6 = 0, s7 = 0;
    int mn = 0x7fffffff, mx = 0;
#pragma unroll 1
    for (int i = 0; i < 8; i++) {
        const unsigned short* grow = tile + i * WW;   // g^2 values
        int best = grow[j];
        int r2 = 1;
        for (int rad = 1; rad < WW; rad++) {
            if (r2 >= best) break;
            int jl = j - rad, jr = j + rad;
            if (jl >= 0) best = min(best, (int)grow[jl] + r2);
            if (jr < WW) best = min(best, (int)grow[jr] + r2);
            r2 += 2 * rad + 1;
        }
        mn = min(mn, best); mx = max(mx, best);
        float soft = soft_of(best);
        float p = fast_sigmoid(pv[i]);
        float fatb = (float)((sfatw[(i << 3) | wsel] >> bsel) & 1u);
        float ps = p * soft;
        s4 += ps;
        s5 += p;
        s6 += p * (1.0f - fatb);
        unsigned int tw = stgw[(i << 3) | wsel];     // warp-uniform word
        if (tw) {
            float t = (float)((tw >> bsel) & 1u);
            s1 += ps * t;
            s2 += p * t;
            s7 += t;
        }
    }
    mn = imin32(mn); mx = imax32(mx);

    // single-stage block reduction
    float v0 = fsum32(s1), v1 = fsum32(s2), v2 = fsum32(s4);
    float v3 = fsum32(s5), v4 = fsum32(s6), v5 = fsum32(s7);
    const int lane = tid & 31, wid = tid >> 5;
    if (lane == 0) {
        sf[wid][0] = v0; sf[wid][1] = v1; sf[wid][2] = v2;
        sf[wid][3] = v3; sf[wid][4] = v4; sf[wid][5] = v5;
        smn8[wid] = mn; smx8[wid] = mx;
    }
    __syncthreads();
    if (tid < 6) {
        float a = 0;
#pragma unroll
        for (int i = 0; i < 8; i++) a += sf[i][tid];
        float* outs[6] = {g_s1, g_s2, g_s4, g_s5, g_s6, g_s7};
        outs[tid][blockIdx.x] = a;
    } else if (tid == 8) {
        int a = smn8[0];
#pragma unroll
        for (int i = 1; i < 8; i++) a = min(a, smn8[i]);
        g_bmin[blockIdx.x] = a;
    } else if (tid == 9) {
        int b = smx8[0];
#pragma unroll
        for (int i = 1; i < 8; i++) b = max(b, smx8[i]);
        g_bmax[blockIdx.x] = b;
    }

    // ---- last-block finisher ----
    if (tid == 0) {
        __threadfence();
        int old = atomicAdd(&g_count, 1);
        s_isLast = (old == RB - 1) ? 1 : 0;
    }
    __syncthreads();
    if (!s_isLast) return;
    if (tid == 0) g_count = 0;
    __threadfence();

    __shared__ float a1[256], a2[256], a4[256], a5[256], a6[256], a7[256];
    __shared__ int amn[256], amx[256];
    {
        const int t = tid;
        const int im = t >> 3, seg = t & 7;
        float S1 = 0, S2 = 0, S4 = 0, S5 = 0, S6 = 0, S7 = 0;
        int mnl = 0x7fffffff, mxl = 0;
#pragma unroll
        for (int q = 0; q < 4; q++) {
            int k = im * 32 + seg * 4 + q;
            S1 += g_s1[k]; S2 += g_s2[k]; S4 += g_s4[k];
            S5 += g_s5[k]; S6 += g_s6[k]; S7 += g_s7[k];
            mnl = min(mnl, g_bmin[k]); mxl = max(mxl, g_bmax[k]);
        }
        a1[t] = S1; a2[t] = S2; a4[t] = S4; a5[t] = S5; a6[t] = S6; a7[t] = S7;
        amn[t] = mnl; amx[t] = mxl;
    }
    __syncthreads();
    if (tid < 32) {
        const int i = tid;
        float S1 = 0, S2 = 0, S4 = 0, S5 = 0, S6 = 0, S7 = 0;
        int mnl = 0x7fffffff, mxl = 0;
#pragma unroll
        for (int s = 0; s < 8; s++) {
            int k = i * 8 + s;
            S1 += a1[k]; S2 += a2[k]; S4 += a4[k];
            S5 += a5[k]; S6 += a6[k]; S7 += a7[k];
            mnl = min(mnl, amn[k]); mxl = max(mxl, amx[k]);
        }
        int fg = 0;
#pragma unroll
        for (int rg = 0; rg < 8; rg++) fg |= g_fgp[i * 8 + rg];
        float inter, card;
        if (fg) {
            float smn = soft_of(mnl);
            float smx = soft_of(mxl);
            float dd = smx - smn;
            float inv = (dd > 0.0f) ? (1.0f / dd) : 1.0f;
            inter = inv * (S1 - smn * S2);
            card  = inv * (S4 - smn * S5) + 0.1f * S6 + S7;
        } else {
            inter = 0.0f;
            card  = (S5 - S2) + S7;
        }
        float tsum = S7;
        inter = fsum32(inter);
        card  = fsum32(card);
        tsum  = fsum32(tsum);
        if (i == 0) {
            float dice = 2.0f * inter / fmaxf(card, 1e-7f);
            float loss = 1.0f - dice;
            out[0] = (tsum > 0.0f) ? loss : 0.0f;
        }
    }
}

extern "C" void kernel_launch(void* const* d_in, const int* in_sizes, int n_in,
                              void* d_out, int out_size) {
    const float* preds = (const float*)d_in[0];
    const float* tg    = (const float*)d_in[1];
    float* out = (float*)d_out;

    k_maskdilate<<<K1B, 256>>>((const float4*)tg);
    k_rowfuse<<<RB, 256>>>(preds, out);
}